// round 3
// baseline (speedup 1.0000x reference)
#include <cuda_runtime.h>

// embedding_pooling: out[b, (c-1)*256 + d] = relu(max_{l: label[b,l]==c} x[b,l,d]), empty->0
// relu + empty-case == fmax chain initialized at 0.
//
// One block per (b, class): gather matching l indices (each l belongs to exactly
// one class -> 1 fmax per loaded element, label-0 rows never loaded), then
// warp-strided float4 max-reduction.
//
// Label dtype: JAX default (x64 disabled) makes "int64" labels int32. A tiny
// sniffer kernel checks the high words of an int64 interpretation; the main
// kernel picks the stride accordingly.

#define BATCH 256
#define LSEQ  512
#define DDIM  256
#define NC    5

__device__ int g_lab_is64;

__global__ void sniff_label_dtype(const int* __restrict__ lab32)
{
    // If the buffer is int64, words at odd indices (high words of values 0..5)
    // are ALL zero. If int32, they are random labels in [0,6) -> OR != 0.
    __shared__ int s_or[256];
    int acc = 0;
    const int t = threadIdx.x;
#pragma unroll
    for (int i = 0; i < 16; i++)                 // first 4096 odd words
        acc |= lab32[2 * (t + 256 * i) + 1];
    s_or[t] = acc;
    __syncthreads();
    for (int s = 128; s > 0; s >>= 1) {
        if (t < s) s_or[t] |= s_or[t + s];
        __syncthreads();
    }
    if (t == 0) g_lab_is64 = (s_or[0] == 0) ? 1 : 0;
}

__global__ __launch_bounds__(256, 8)
void embedding_pooling_kernel(const float* __restrict__ x,
                              const int* __restrict__ lab32,
                              float* __restrict__ out)
{
    __shared__ int    s_idx[LSEQ];
    __shared__ int    s_cnt;
    __shared__ float4 s_red[8][64];

    const int tid = threadIdx.x;
    const int b   = blockIdx.x / NC;
    const int c   = (blockIdx.x % NC) + 1;

    if (tid == 0) s_cnt = 0;
    __syncthreads();

    // ---- Phase 1: gather l with label == c (order irrelevant for max)
    const int is64 = g_lab_is64;
    const int* lab_row = lab32 + ((size_t)b * LSEQ << is64);
    for (int l = tid; l < LSEQ; l += 256) {
        if (__ldg(&lab_row[l << is64]) == c) {   // int64: low word at 2*l
            int p = atomicAdd(&s_cnt, 1);
            s_idx[p] = l;
        }
    }
    __syncthreads();
    const int n = s_cnt;

    // ---- Phase 2: warp-strided max over gathered rows.
    const int w = tid >> 5;
    const int q = tid & 31;
    const float4* X4 = (const float4*)x;
    const int base_row = b * LSEQ;

    float4 m0 = make_float4(0.f, 0.f, 0.f, 0.f);
    float4 m1 = make_float4(0.f, 0.f, 0.f, 0.f);

#pragma unroll 2
    for (int j = w; j < n; j += 8) {
        const int l = s_idx[j];
        const float4* row = X4 + (size_t)(base_row + l) * (DDIM / 4);
        const float4 v0 = row[q];
        const float4 v1 = row[32 + q];
        m0.x = fmaxf(m0.x, v0.x); m0.y = fmaxf(m0.y, v0.y);
        m0.z = fmaxf(m0.z, v0.z); m0.w = fmaxf(m0.w, v0.w);
        m1.x = fmaxf(m1.x, v1.x); m1.y = fmaxf(m1.y, v1.y);
        m1.z = fmaxf(m1.z, v1.z); m1.w = fmaxf(m1.w, v1.w);
    }

    s_red[w][q]      = m0;
    s_red[w][32 + q] = m1;
    __syncthreads();

    // ---- Phase 3: reduce across 8 warps; float4 store.
    if (tid < 64) {
        float4 m = s_red[0][tid];
#pragma unroll
        for (int g = 1; g < 8; g++) {
            const float4 v = s_red[g][tid];
            m.x = fmaxf(m.x, v.x); m.y = fmaxf(m.y, v.y);
            m.z = fmaxf(m.z, v.z); m.w = fmaxf(m.w, v.w);
        }
        float4* O4 = (float4*)out;
        O4[(size_t)b * (NC * (DDIM / 4)) + (size_t)(c - 1) * (DDIM / 4) + tid] = m;
    }
}

extern "C" void kernel_launch(void* const* d_in, const int* in_sizes, int n_in,
                              void* d_out, int out_size)
{
    const float* x     = (const float*)d_in[0];
    const int*   lab32 = (const int*)d_in[1];
    float*       out   = (float*)d_out;

    sniff_label_dtype<<<1, 256>>>(lab32);
    embedding_pooling_kernel<<<BATCH * NC, 256>>>(x, lab32, out);
}